// round 16
// baseline (speedup 1.0000x reference)
#include <cuda_runtime.h>
#include <cuda_bf16.h>

// Problem constants (fixed by the reference)
#define BMAX 524288
constexpr int   C_CLS = 330;
constexpr int   NF2   = C_CLS / 2;               // 165 float2 per row
constexpr float TAU   = 5.799092654460526f;      // ln(330)
constexpr float LAM   = 0.25f;
constexpr float EPSV  = 0.1f;
constexpr float E_F   = 2.718281828459045f;
constexpr float NEG2E = -0.7357588823428847f;    // -2/e

// Allocation-free scratch: __device__ globals. Zero-initialized at load;
// K2's finalize resets the accumulators so every graph replay starts clean.
__device__ float    g_c[BMAX];                   // per-row weighted contribution
__device__ double   g_acc;                       // total sum
__device__ unsigned g_count;

// ---------------------------------------------------------------------------
// Kernel 1: one warp per row (R13-proven float2 streamer, no max subtraction)
// PLUS a barrier-free lane-0 tail that solves Lambert W for this row and
// writes ONE pre-weighted scalar:
//   contrib = (EPS/C)*sm_i + (1-EPS)*[(l_i-tau)*sigma + lam*w^2]
// No __syncthreads anywhere: the ~700-cycle Halley chain on lane 0 hides
// under the streaming of the other resident warps (issue util ~15%).
// ---------------------------------------------------------------------------
__global__ __launch_bounds__(256) void row_kernel(
    const float* __restrict__ x, const int* __restrict__ tgt, int B)
{
    int row  = blockIdx.x * 8 + (threadIdx.x >> 5);
    if (row >= B) return;
    int lane = threadIdx.x & 31;

    int t = __ldg(tgt + row);                              // prefetch (broadcast)

    const float2* p = reinterpret_cast<const float2*>(x + (size_t)row * C_CLS);

    float sx = 0.f, se = 0.f;
#pragma unroll
    for (int k = 0; k < 6; k++) {
        int idx = k * 32 + lane;
        if (idx < NF2) {
            float2 u = __ldg(p + idx);
            sx += u.x + u.y;
            se += __expf(u.x) + __expf(u.y);               // MUFU, fires per load
        }
    }

    float xt = __ldg(x + (size_t)row * C_CLS + t);         // L1 hit (row in flight)

#pragma unroll
    for (int o = 16; o > 0; o >>= 1) {                     // interleaved trees
        sx += __shfl_xor_sync(0xffffffffu, sx, o);
        se += __shfl_xor_sync(0xffffffffu, se, o);
    }

    if (lane == 0) {
        float logZ = logf(se);                             // precise log (1/row)
        float l    = logZ - xt;                            // l_i
        float sm   = (float)C_CLS * logZ - sx;             // -sum_c log p

        // Lambert W (reference recipe: series/log1p guess + Halley, MUFU exp,
        // precise divisions, 6 iterations — measured rel_err 1.6e-4 config)
        float y  = 0.5f * fmaxf(NEG2E, (l - TAU) * 4.0f);  // /LAM, LAM=0.25
        float pb = sqrtf(fmaxf(2.f * (E_F * y + 1.f), 0.f));
        float wbp = -1.f + pb - pb * pb * (1.f / 3.f)
                    + (11.f / 72.f) * pb * pb * pb;
        float w = (y < 0.3f) ? wbp : log1pf(y);
#pragma unroll
        for (int it = 0; it < 6; it++) {
            float ew   = __expf(w);                        // MUFU EX2
            float f    = w * ew - y;
            float wp1  = w + 1.f;
            float swp1 = (fabsf(wp1) < 1e-12f) ? 1e-12f : wp1;
            float den  = ew * wp1 - (w + 2.f) * f / (2.f * swp1);
            float sden = (fabsf(den) < 1e-30f) ? 1e-30f : den;
            float step = (fabsf(f) < 1e-30f) ? 0.f : f / sden;
            w -= step;
        }
        float sigma = __expf(-w);
        float sup   = (l - TAU) * sigma + LAM * w * w;

        g_c[row] = (EPSV / (float)C_CLS) * sm + (1.f - EPSV) * sup;
    }
}

// ---------------------------------------------------------------------------
// Kernel 2: pure sum of g_c (2 MB) + last-block finalize (writes out[0] =
// mean, resets accumulators for deterministic graph replay).
// ---------------------------------------------------------------------------
__global__ __launch_bounds__(256) void reduce_kernel(float* __restrict__ out, int B)
{
    __shared__ float s1[32];
    __shared__ bool  s_last;

    float s = 0.f;
    int stride = gridDim.x * blockDim.x;
    for (int i = blockIdx.x * blockDim.x + threadIdx.x; i < B; i += stride)
        s += g_c[i];

    int lane = threadIdx.x & 31, wid = threadIdx.x >> 5;
#pragma unroll
    for (int o = 16; o > 0; o >>= 1)
        s += __shfl_xor_sync(0xffffffffu, s, o);
    if (lane == 0) s1[wid] = s;
    __syncthreads();
    if (wid == 0) {
        int nw = blockDim.x >> 5;
        float a = (lane < nw) ? s1[lane] : 0.f;
#pragma unroll
        for (int o = 16; o > 0; o >>= 1)
            a += __shfl_xor_sync(0xffffffffu, a, o);
        if (lane == 0)
            atomicAdd(&g_acc, (double)a);
    }

    // last-block finalize + reset (graph-replay deterministic)
    __threadfence();
    if (threadIdx.x == 0) {
        unsigned c = atomicAdd(&g_count, 1u);
        s_last = (c == gridDim.x - 1);
    }
    __syncthreads();
    if (s_last && threadIdx.x == 0) {
        out[0]  = (float)(g_acc / (double)B);
        g_acc   = 0.0;
        g_count = 0u;
    }
}

// ---------------------------------------------------------------------------
extern "C" void kernel_launch(void* const* d_in, const int* in_sizes, int n_in,
                              void* d_out, int out_size)
{
    const float* x   = (const float*)d_in[0];   // output [B, 330] f32
    const int*   tgt = (const int*)d_in[1];     // target [B] i32
    int B = in_sizes[1];
    if (B > BMAX) B = BMAX;

    int nblk = (B + 7) / 8;                     // 8 warps (rows) per block
    row_kernel<<<nblk, 256>>>(x, tgt, B);
    reduce_kernel<<<1024, 256>>>((float*)d_out, B);
}

// round 17
// speedup vs baseline: 1.6117x; 1.6117x over previous
#include <cuda_runtime.h>
#include <cuda_bf16.h>

// Problem constants (fixed by the reference)
constexpr int   C_CLS = 330;
constexpr int   NF2   = C_CLS / 2;               // 165 float2 per row
constexpr float TAU   = 5.799092654460526f;      // ln(330)
constexpr float LAM   = 0.25f;
constexpr float EPSV  = 0.1f;
constexpr float E_F   = 2.718281828459045f;
constexpr float NEG2E = -0.7357588823428847f;    // -2/e

constexpr int ROWS_PER_WARP = 8;                 // tail amortization factor
constexpr int WARPS_PER_BLK = 8;
constexpr int ROWS_PER_BLK  = ROWS_PER_WARP * WARPS_PER_BLK;  // 64

// Allocation-free scratch: __device__ globals (zero-init at load; finalize
// resets them so every graph replay starts clean).
__device__ double   g_acc;
__device__ unsigned g_count;

// ---------------------------------------------------------------------------
// Single fused kernel, no inter-warp sync in the hot path:
//  - each warp streams 8 rows (R13-proven float2 / no-max softmax loop);
//    xor-butterfly leaves the full (sx, se) on ALL lanes; lane j keeps row j.
//  - ONE lane-parallel Halley chain per 8 rows (lanes 0-7, each its own row)
//    -> serial-tail cost ~110 cyc/row, staggered across resident blocks.
//  - one pre-weighted contribution atomicAdd(double) per warp per chunk.
//  - last-block finalize writes out[0] and resets state (graph-replay safe).
// ---------------------------------------------------------------------------
__global__ __launch_bounds__(256) void fused_kernel(
    const float* __restrict__ x, const int* __restrict__ tgt,
    float* __restrict__ out, int B)
{
    __shared__ bool s_last;

    int lane = threadIdx.x & 31;
    int wid  = threadIdx.x >> 5;
    int base = (blockIdx.x * WARPS_PER_BLK + wid) * ROWS_PER_WARP;

    int nrows = B - base;
    if (nrows < 0) nrows = 0;
    if (nrows > ROWS_PER_WARP) nrows = ROWS_PER_WARP;

    float myl = 0.f, mysm = 0.f;

    for (int j = 0; j < nrows; j++) {
        int row = base + j;
        int t = __ldg(tgt + row);                          // prefetch (broadcast)

        const float2* p = reinterpret_cast<const float2*>(x + (size_t)row * C_CLS);
        float sx = 0.f, se = 0.f;
#pragma unroll
        for (int k = 0; k < 6; k++) {
            int idx = k * 32 + lane;
            if (idx < NF2) {
                float2 u = __ldg(p + idx);
                sx += u.x + u.y;
                se += __expf(u.x) + __expf(u.y);           // MUFU, fires per load
            }
        }
        float xt = __ldg(x + (size_t)row * C_CLS + t);     // L1 hit (row in flight)

#pragma unroll
        for (int o = 16; o > 0; o >>= 1) {                 // butterfly: full sums
            sx += __shfl_xor_sync(0xffffffffu, sx, o);     // land on ALL lanes
            se += __shfl_xor_sync(0xffffffffu, se, o);
        }

        float logZ = logf(se);                             // same value all lanes
        float l    = logZ - xt;
        float sm   = (float)C_CLS * logZ - sx;
        myl  = (lane == j) ? l  : myl;                     // lane j owns row j
        mysm = (lane == j) ? sm : mysm;
    }

    // ---- lane-parallel Halley tail: lanes 0..nrows-1, one row each ----
    float contrib = 0.f;
    if (lane < nrows) {
        float l = myl;
        // Reference recipe (R10/R13-proven config: series/log1p guess,
        // 6 Halley iterations, MUFU __expf, precise divisions, same clamps)
        float y  = 0.5f * fmaxf(NEG2E, (l - TAU) * 4.0f);  // /LAM, LAM=0.25
        float pb = sqrtf(fmaxf(2.f * (E_F * y + 1.f), 0.f));
        float wbp = -1.f + pb - pb * pb * (1.f / 3.f)
                    + (11.f / 72.f) * pb * pb * pb;
        float w = (y < 0.3f) ? wbp : log1pf(y);
#pragma unroll
        for (int it = 0; it < 6; it++) {
            float ew   = __expf(w);                        // MUFU EX2
            float f    = w * ew - y;
            float wp1  = w + 1.f;
            float swp1 = (fabsf(wp1) < 1e-12f) ? 1e-12f : wp1;
            float den  = ew * wp1 - (w + 2.f) * f / (2.f * swp1);
            float sden = (fabsf(den) < 1e-30f) ? 1e-30f : den;
            float step = (fabsf(f) < 1e-30f) ? 0.f : f / sden;
            w -= step;
        }
        float sigma = __expf(-w);
        float sup   = (l - TAU) * sigma + LAM * w * w;

        contrib = (EPSV / (float)C_CLS) * mysm + (1.f - EPSV) * sup;
    }

#pragma unroll
    for (int o = 16; o > 0; o >>= 1)
        contrib += __shfl_xor_sync(0xffffffffu, contrib, o);

    if (lane == 0 && nrows > 0)
        atomicAdd(&g_acc, (double)contrib);                // 1 per 8 rows

    // ---- last-block finalize + reset (graph-replay deterministic) ----
    __threadfence();
    __syncthreads();
    if (threadIdx.x == 0) {
        unsigned c = atomicAdd(&g_count, 1u);
        s_last = (c == gridDim.x - 1);
    }
    __syncthreads();
    if (s_last && threadIdx.x == 0) {
        out[0]  = (float)(g_acc / (double)B);
        g_acc   = 0.0;
        g_count = 0u;
    }
}

// ---------------------------------------------------------------------------
extern "C" void kernel_launch(void* const* d_in, const int* in_sizes, int n_in,
                              void* d_out, int out_size)
{
    const float* x   = (const float*)d_in[0];   // output [B, 330] f32
    const int*   tgt = (const int*)d_in[1];     // target [B] i32
    int B = in_sizes[1];

    int nblk = (B + ROWS_PER_BLK - 1) / ROWS_PER_BLK;      // 8192 for B=524288
    fused_kernel<<<nblk, 256>>>(x, tgt, (float*)d_out, B);
}